// round 16
// baseline (speedup 1.0000x reference)
#include <cuda_runtime.h>
#include <cuda_fp16.h>
#include <cstdint>

// ============================================================================
// out[i,j] = w3 . relu(W2 . relu(hx_i + hy_j + b1) + b2) + b3
// B = 512, H = 512, DX = DY = 128
// ============================================================================
#define BB 512
#define HH 512
#define NCTA 148          // persistent, 1 CTA/SM
#define NTILE 2048        // 128-pair tiles (8i x 16j)

__device__ __align__(128)  float  g_hx[BB * HH];           // x@W1[:, :128]^T + b1
__device__ __align__(128)  float  g_hy[BB * HH];           // y@W1[:, 128:]^T
// W2 fp16, pre-swizzled: 16 slabs (sid = nc*4 + kq) of 32KB (n128 x k128).
// slab: row n_local (0..127) * 256B; 16B chunk c (=k_local>>3, 0..15) at
// ((c ^ (n_local&7)) << 4); fp16 pair at (k_local&7)*2.
__device__ __align__(1024) unsigned char g_Wsw[HH * HH * 2];

// k_main SMEM layout (dynamic, bytes)
#define OFF_A    0                         // 128 rows x 1024B (fp16, swizzled)
#define OFF_W(s) (131072 + (s) * 32768)    // 2 x 32KB W slabs
#define OFF_B2   196608                    // 512 f32
#define OFF_W3   198656                    // 512 f32
#define OFF_MB   200704                    // 2 mbarriers (16B) + 2 counters (8B)
#define OFF_PART 200736                    // 128 x 4 f32 epilogue scratch
#define SMEM_BYTES 202784

static __device__ __forceinline__ uint32_t smem_u32(const void* p) {
    uint32_t a;
    asm("{ .reg .u64 t; cvta.to.shared.u64 t, %1; cvt.u32.u64 %0, t; }" : "=r"(a) : "l"(p));
    return a;
}
#define MBAR_INIT(addr, cnt) \
    asm volatile("mbarrier.init.shared.b64 [%0], %1;" :: "r"(addr), "r"(cnt) : "memory")
#define MBAR_EXPECT_TX(addr, bytes) \
    asm volatile("mbarrier.arrive.expect_tx.shared.b64 _, [%0], %1;" :: "r"(addr), "r"(bytes) : "memory")
#define MBAR_WAIT(addr, ph) do {                                                \
    uint32_t _m = (addr), _p = (ph), _d;                                        \
    asm volatile("{\n\t.reg .pred p;\n\t"                                       \
        "mbarrier.try_wait.parity.acquire.cta.shared::cta.b64 p, [%1], %2;\n\t" \
        "selp.b32 %0, 1, 0, p;\n\t}" : "=r"(_d) : "r"(_m), "r"(_p) : "memory"); \
    if (!_d) {                                                                  \
        asm volatile("{\n\t.reg .pred P;\n\tWL%=:\n\t"                          \
            "mbarrier.try_wait.parity.acquire.cta.shared::cta.b64 P, [%0], %1, 0x989680;\n\t" \
            "@P bra.uni WD%=;\n\tbra.uni WL%=;\n\tWD%=:\n\t}"                   \
            :: "r"(_m), "r"(_p) : "memory");                                    \
    }                                                                           \
} while (0)
static __device__ __forceinline__ void bulk_g2s(uint32_t dst, const void* src,
                                                uint32_t bytes, uint32_t mbar) {
    asm volatile(
        "cp.async.bulk.shared::cluster.global.mbarrier::complete_tx::bytes [%0], [%1], %2, [%3];"
        :: "r"(dst), "l"(src), "r"(bytes), "r"(mbar) : "memory");
}
static __device__ __forceinline__ void ldsm_x4(uint32_t& r0, uint32_t& r1, uint32_t& r2,
                                               uint32_t& r3, uint32_t addr) {
    asm volatile("ldmatrix.sync.aligned.m8n8.x4.shared.b16 {%0,%1,%2,%3}, [%4];"
                 : "=r"(r0), "=r"(r1), "=r"(r2), "=r"(r3) : "r"(addr));
}
static __device__ __forceinline__ void mma16816(float* d, const uint32_t* a, const uint32_t* b) {
    asm volatile(
        "mma.sync.aligned.m16n8k16.row.col.f32.f16.f16.f32 "
        "{%0,%1,%2,%3}, {%4,%5,%6,%7}, {%8,%9}, {%0,%1,%2,%3};"
        : "+f"(d[0]), "+f"(d[1]), "+f"(d[2]), "+f"(d[3])
        : "r"(a[0]), "r"(a[1]), "r"(a[2]), "r"(a[3]), "r"(b[0]), "r"(b[1]));
}

// ============================================================================
// Kernel 1: prep.  Blocks 0..255: first linear (2i x 4h register microtile,
// vectorized smem).  Blocks 256..767: W2 quant/swizzle (16 slabs of 32KB).
// ============================================================================
__global__ void __launch_bounds__(256) k_prep(const float* __restrict__ x,
                                              const float* __restrict__ y,
                                              const float* __restrict__ W1,
                                              const float* __restrict__ b1,
                                              const float* __restrict__ W2) {
    int b = blockIdx.x;
    if (b >= 256) {
        // quant: 2 consecutive h per thread; layout = 16 slabs of 32KB
        int idx = ((b - 256) * 256 + threadIdx.x) * 2;
        int n = idx >> 9, h = idx & 511;
        int n_local = n & 127;
        int sid = (n >> 7) * 4 + (h >> 7);
        int k_local = h & 127;
        uint32_t c = (uint32_t)(k_local >> 3);
        uint32_t off = (uint32_t)n_local * 256 +
                       ((c ^ (uint32_t)(n_local & 7)) << 4) + (uint32_t)(k_local & 7) * 2;
        float2 v = *(const float2*)(W2 + (size_t)n * HH + h);
        __half2 hv;
        hv.x = __float2half_rn(v.x);
        hv.y = __float2half_rn(v.y);
        *(uint32_t*)(g_Wsw + (size_t)sid * 32768 + off) = *(uint32_t*)&hv;
        return;
    }
    // ---- first linear: block tile 32i x 64h, thread microtile 2i x 4h ----
    __shared__ float xs[32 * 130];     // row-major [i][d], pad 130 (8B-aligned rows)
    __shared__ float ws_t[128 * 68];   // transposed [d][h], pad 68 (16B-aligned rows)
    int path = b >> 7;
    int rem = b & 127;
    int i0 = (rem & 15) * 32, h0 = (rem >> 4) * 64;
    const float* src = path ? y : x;
    int colOff = path ? 128 : 0;

    for (int v = threadIdx.x; v < 32 * 128; v += 256) {
        int i = v >> 7, d = v & 127;
        xs[i * 130 + d] = src[(i0 + i) * 128 + d];
    }
    for (int v = threadIdx.x; v < 64 * 128; v += 256) {
        int h = v >> 7, d = v & 127;
        ws_t[d * 68 + h] = W1[(h0 + h) * 256 + colOff + d];
    }
    __syncthreads();

    int ti = threadIdx.x & 15, th = threadIdx.x >> 4;
    const float* x0 = xs + (2 * ti) * 130;
    const float* x1 = x0 + 130;
    const float* wq = ws_t + th * 4;
    float acc[2][4] = {{0.f, 0.f, 0.f, 0.f}, {0.f, 0.f, 0.f, 0.f}};
    #pragma unroll 4
    for (int d = 0; d < 128; d += 2) {
        float2 xa = *(const float2*)(x0 + d);
        float2 xb = *(const float2*)(x1 + d);
        float4 w0 = *(const float4*)(wq + d * 68);
        float4 w1 = *(const float4*)(wq + (d + 1) * 68);
        acc[0][0] = fmaf(xa.x, w0.x, acc[0][0]);
        acc[0][1] = fmaf(xa.x, w0.y, acc[0][1]);
        acc[0][2] = fmaf(xa.x, w0.z, acc[0][2]);
        acc[0][3] = fmaf(xa.x, w0.w, acc[0][3]);
        acc[1][0] = fmaf(xb.x, w0.x, acc[1][0]);
        acc[1][1] = fmaf(xb.x, w0.y, acc[1][1]);
        acc[1][2] = fmaf(xb.x, w0.z, acc[1][2]);
        acc[1][3] = fmaf(xb.x, w0.w, acc[1][3]);
        acc[0][0] = fmaf(xa.y, w1.x, acc[0][0]);
        acc[0][1] = fmaf(xa.y, w1.y, acc[0][1]);
        acc[0][2] = fmaf(xa.y, w1.z, acc[0][2]);
        acc[0][3] = fmaf(xa.y, w1.w, acc[0][3]);
        acc[1][0] = fmaf(xb.y, w1.x, acc[1][0]);
        acc[1][1] = fmaf(xb.y, w1.y, acc[1][1]);
        acc[1][2] = fmaf(xb.y, w1.z, acc[1][2]);
        acc[1][3] = fmaf(xb.y, w1.w, acc[1][3]);
    }

    float* dst = path ? g_hy : g_hx;
    int hb = h0 + th * 4;
    float bv0 = path ? 0.f : b1[hb + 0];
    float bv1 = path ? 0.f : b1[hb + 1];
    float bv2 = path ? 0.f : b1[hb + 2];
    float bv3 = path ? 0.f : b1[hb + 3];
    #pragma unroll
    for (int ii = 0; ii < 2; ii++) {
        int i = i0 + 2 * ti + ii;
        float4 o;
        o.x = acc[ii][0] + bv0;
        o.y = acc[ii][1] + bv1;
        o.z = acc[ii][2] + bv2;
        o.w = acc[ii][3] + bv3;
        *(float4*)(dst + (size_t)i * HH + hb) = o;
    }
}

// ============================================================================
// Kernel 2: persistent main pair-GEMM + fused epilogue.
//   grid 148 (1 CTA/SM), block 256 (8 warps).  Tile: 128 pairs (8i x 16j),
//   16 steps of 32KB W (n128 x k128), pipeline continuous across tiles
//   (global step gst).  Warp grid 2m x 4n, warp tile m64 x n32.
//   A-build fully register-prefetched (hyv[16] + hxv[8]).
// ============================================================================
__global__ void __launch_bounds__(256, 1) k_main(const float* __restrict__ b2g,
                                                 const float* __restrict__ w3g,
                                                 const float* __restrict__ b3g,
                                                 float* __restrict__ out) {
    extern __shared__ __align__(1024) unsigned char smem[];
    uint32_t sb = smem_u32(smem);
    int tid = threadIdx.x, wid = tid >> 5, lane = tid & 31;

    float* b2s = (float*)(smem + OFF_B2);
    float* w3s = (float*)(smem + OFF_W3);
    float* part = (float*)(smem + OFF_PART);

    // tiles handled by this CTA
    int ntiles = 0;
    for (int t = blockIdx.x; t < NTILE; t += NCTA) ntiles++;
    int total_gst = ntiles * 16;

    // ---- one-time init: mbarriers/counters + first two W slabs + b2/w3 ----
    if (tid == 0) {
        MBAR_INIT(sb + OFF_MB + 0, 1);
        MBAR_INIT(sb + OFF_MB + 8, 1);
        *(int*)(smem + OFF_MB + 16) = 0;
        *(int*)(smem + OFF_MB + 20) = 0;
        asm volatile("fence.proxy.async.shared::cta;" ::: "memory");
        MBAR_EXPECT_TX(sb + OFF_MB + 0, 32768u);
        bulk_g2s(sb + OFF_W(0), g_Wsw + 0 * 32768, 32768u, sb + OFF_MB + 0);
        MBAR_EXPECT_TX(sb + OFF_MB + 8, 32768u);
        bulk_g2s(sb + OFF_W(1), g_Wsw + 1 * 32768, 32768u, sb + OFF_MB + 8);
    }
    for (int v = tid; v < 512; v += 256) {
        b2s[v] = b2g[v];
        w3s[v] = w3g[v];
    }
    float b3v = b3g[0];

    // ---- lane geometry (tile-independent): warp grid 2m x 4n, m64 x n32 ----
    int wm = wid >> 2;          // 0..1 -> m0 = wm*64
    int wn = wid & 3;           // 0..3 -> n0 = wn*32 within n-chunk 128
    int m0 = wm * 64, n0 = wn * 32;

    uint32_t x7 = (uint32_t)(lane & 7);
    uint32_t aHi = (uint32_t)(lane >> 4);
    uint32_t aRow[4];
    #pragma unroll
    for (int mi = 0; mi < 4; mi++)
        aRow[mi] = sb + OFF_A + (uint32_t)(m0 + mi * 16 + (lane & 15)) * 1024;
    uint32_t bRowOff = (uint32_t)(n0 + (lane & 7) + ((lane >> 4) << 3)) * 256;
    uint32_t bHi = (uint32_t)((lane >> 3) & 1);

    int gst = 0;

    #pragma unroll 1
    for (int t = blockIdx.x; t < NTILE; t += NCTA) {
        int i0 = (t >> 5) * 8, j0 = (t & 31) * 16;

        // ---- tile boundary: all warps done with previous A / part ----
        __syncthreads();

        // ---- build A = relu(hx_i + hy_j) fp16; hx AND hy fully prefetched ----
        {
            int kk = tid;  // half2 column 0..255
            float2 hyv[16];
            #pragma unroll
            for (int j = 0; j < 16; j++)
                hyv[j] = ((const float2*)(g_hy + (j0 + j) * HH))[kk];
            float2 hxv[8];
            #pragma unroll
            for (int ig = 0; ig < 8; ig++)
                hxv[ig] = ((const float2*)(g_hx + (i0 + ig) * HH))[kk];
            uint32_t base = sb + OFF_A + (uint32_t)(kk & 3) * 4;
            uint32_t chunk = (uint32_t)(kk >> 2);
            #pragma unroll
            for (int ig = 0; ig < 8; ig++) {
                #pragma unroll
                for (int j = 0; j < 16; j++) {
                    float s0 = hxv[ig].x + hyv[j].x;
                    float s1 = hxv[ig].y + hyv[j].y;
                    uint32_t h2, r;
                    asm("cvt.rn.f16x2.f32 %0, %1, %2;" : "=r"(h2) : "f"(s1), "f"(s0));
                    asm("max.f16x2 %0, %1, %2;" : "=r"(r) : "r"(h2), "r"(0u));
                    uint32_t p = (uint32_t)(ig * 16 + j);
                    uint32_t addr = base + p * 1024 + ((chunk ^ (p & 7)) << 4);
                    asm volatile("st.shared.b32 [%0], %1;"
                                 :: "r"(addr), "r"(r) : "memory");
                }
            }
        }
        __syncthreads();   // A visible (covers one-time init on first tile)

        float d[4][4][4];                 // [mi][ni][q]
        float rowacc[4][2];               // [mi][row half]
        #pragma unroll
        for (int mi = 0; mi < 4; mi++) { rowacc[mi][0] = 0.f; rowacc[mi][1] = 0.f; }

        #pragma unroll 1
        for (int st = 0; st < 16; st++, gst++) {
            int s = gst & 1, kq = st & 3;
            MBAR_WAIT(sb + OFF_MB + s * 8, (gst >> 1) & 1);

            if (kq == 0) {
                #pragma unroll
                for (int mi = 0; mi < 4; mi++)
                    #pragma unroll
                    for (int ni = 0; ni < 4; ni++)
                        #pragma unroll
                        for (int q = 0; q < 4; q++) d[mi][ni][q] = 0.f;
            }

            uint32_t bBase = sb + OFF_W(s) + bRowOff;
            uint32_t aChunk0 = (uint32_t)(kq * 16);

            #pragma unroll
            for (int kk = 0; kk < 8; kk++) {
                uint32_t aswz = (((aChunk0 + (uint32_t)(kk << 1) + aHi) ^ x7) << 4);
                uint32_t bswz = ((((uint32_t)(kk << 1) + bHi) ^ x7) << 4);
                uint32_t a[4][4], b0[4], b1[4];
                #pragma unroll
                for (int mi = 0; mi < 4; mi++)
                    ldsm_x4(a[mi][0], a[mi][1], a[mi][2], a[mi][3], aRow[mi] + aswz);
                ldsm_x4(b0[0], b0[1], b0[2], b0[3], bBase + bswz);
                ldsm_x4(b1[0], b1[1], b1[2], b1[3], bBase + 16 * 256 + bswz);
                #pragma unroll
                for (int mi = 0; mi < 4; mi++) {
                    mma16816(d[mi][0], a[mi], b0 + 0);
                    mma16816(d[mi][1], a[mi], b0 + 2);
                    mma16816(d[mi][2], a[mi], b1 + 0);
                    mma16816(d[mi][3], a[mi], b1 + 2);
                }
            }

            // refetch bump EARLY (before fold): all W(s) reads by this warp done
            if (lane == 0) {
                int old;
                asm volatile("atom.shared.add.s32 %0, [%1], 1;"
                             : "=r"(old) : "r"(sb + OFF_MB + 16 + s * 4) : "memory");
                if ((old & 7) == 7 && gst + 2 < total_gst) {
                    MBAR_EXPECT_TX(sb + OFF_MB + s * 8, 32768u);
                    bulk_g2s(sb + OFF_W(s), g_Wsw + (size_t)((gst + 2) & 15) * 32768,
                             32768u, sb + OFF_MB + s * 8);
                }
            }

            if (kq == 3) {
                // fold: rowacc += sum_n relu(D + b2[n]) * w3[n]
                int ncol = (st >> 2) * 128 + n0 + (lane & 3) * 2;
                #pragma unroll
                for (int ni = 0; ni < 4; ni++) {
                    int c0 = ncol + ni * 8, c1 = c0 + 1;
                    float bb0 = b2s[c0], bb1 = b2s[c1];
                    float ww0 = w3s[c0], ww1 = w3s[c1];
                    #pragma unroll
                    for (int mi = 0; mi < 4; mi++) {
                        rowacc[mi][0] = fmaf(fmaxf(d[mi][ni][0] + bb0, 0.f), ww0, rowacc[mi][0]);
                        rowacc[mi][0] = fmaf(fmaxf(d[mi][ni][1] + bb1, 0.f), ww1, rowacc[mi][0]);
                        rowacc[mi][1] = fmaf(fmaxf(d[mi][ni][2] + bb0, 0.f), ww0, rowacc[mi][1]);
                        rowacc[mi][1] = fmaf(fmaxf(d[mi][ni][3] + bb1, 0.f), ww1, rowacc[mi][1]);
                    }
                }
            }
        }

        // ---- epilogue: reduce across 4 lanes/row, then across 4 n-warps ----
        #pragma unroll
        for (int mi = 0; mi < 4; mi++)
            #pragma unroll
            for (int rh = 0; rh < 2; rh++) {
                rowacc[mi][rh] += __shfl_xor_sync(0xFFFFFFFFu, rowacc[mi][rh], 1);
                rowacc[mi][rh] += __shfl_xor_sync(0xFFFFFFFFu, rowacc[mi][rh], 2);
            }

        if ((lane & 3) == 0) {
            int g = lane >> 2;
            #pragma unroll
            for (int mi = 0; mi < 4; mi++)
                #pragma unroll
                for (int rh = 0; rh < 2; rh++) {
                    int m = m0 + mi * 16 + rh * 8 + g;
                    part[m * 4 + wn] = rowacc[mi][rh];
                }
        }
        __syncthreads();

        if (tid < 128) {
            float res = part[tid * 4 + 0] + part[tid * 4 + 1] +
                        part[tid * 4 + 2] + part[tid * 4 + 3] + b3v;
            int i = i0 + (tid >> 4);
            int j = j0 + (tid & 15);
            out[i * BB + j] = res;
        }
    }
}

// ============================================================================
// Host launcher
// ============================================================================
extern "C" void kernel_launch(void* const* d_in, const int* in_sizes, int n_in,
                              void* d_out, int out_size) {
    const float* x  = (const float*)d_in[0];
    const float* y  = (const float*)d_in[1];
    const float* W1 = (const float*)d_in[2];
    const float* b1 = (const float*)d_in[3];
    const float* W2 = (const float*)d_in[4];
    const float* b2 = (const float*)d_in[5];
    const float* W3 = (const float*)d_in[6];
    const float* b3 = (const float*)d_in[7];
    float* out = (float*)d_out;

    cudaFuncSetAttribute(k_main, cudaFuncAttributeMaxDynamicSharedMemorySize, SMEM_BYTES);

    k_prep<<<768, 256>>>(x, y, W1, b1, W2);
    k_main<<<NCTA, 256, SMEM_BYTES>>>(b2, W3, b3, out);
}

// round 17
// speedup vs baseline: 1.0100x; 1.0100x over previous
#include <cuda_runtime.h>
#include <cuda_fp16.h>
#include <cstdint>

// ============================================================================
// out[i,j] = w3 . relu(W2 . relu(hx_i + hy_j + b1) + b2) + b3
// B = 512, H = 512, DX = DY = 128
// ============================================================================
#define BB 512
#define HH 512
#define NCTA 148          // persistent, 1 CTA/SM
#define NTILE 2048        // 128-pair tiles (8i x 16j)

__device__ __align__(128)  float  g_hx[BB * HH];           // x@W1[:, :128]^T + b1
__device__ __align__(128)  float  g_hy[BB * HH];           // y@W1[:, 128:]^T
// W2 fp16, pre-swizzled: 16 slabs (sid = nc*4 + kq) of 32KB (n128 x k128).
// slab: row n_local (0..127) * 256B; 16B chunk c (=k_local>>3, 0..15) at
// ((c ^ (n_local&7)) << 4); fp16 pair at (k_local&7)*2.
__device__ __align__(1024) unsigned char g_Wsw[HH * HH * 2];

// k_main SMEM layout (dynamic, bytes)
#define OFF_A    0                         // 128 rows x 1024B (fp16, swizzled)
#define OFF_W(s) (131072 + (s) * 32768)    // 2 x 32KB W slabs
#define OFF_B2   196608                    // 512 f32
#define OFF_W3   198656                    // 512 f32
#define OFF_MB   200704                    // 2 mbarriers (16B) + 2 counters (8B)
#define OFF_PART 200736                    // 128 x 4 f32 epilogue scratch
#define SMEM_BYTES 202784

static __device__ __forceinline__ uint32_t smem_u32(const void* p) {
    uint32_t a;
    asm("{ .reg .u64 t; cvta.to.shared.u64 t, %1; cvt.u32.u64 %0, t; }" : "=r"(a) : "l"(p));
    return a;
}
#define MBAR_INIT(addr, cnt) \
    asm volatile("mbarrier.init.shared.b64 [%0], %1;" :: "r"(addr), "r"(cnt) : "memory")
#define MBAR_EXPECT_TX(addr, bytes) \
    asm volatile("mbarrier.arrive.expect_tx.shared.b64 _, [%0], %1;" :: "r"(addr), "r"(bytes) : "memory")
#define MBAR_WAIT(addr, ph) do {                                                \
    uint32_t _m = (addr), _p = (ph), _d;                                        \
    asm volatile("{\n\t.reg .pred p;\n\t"                                       \
        "mbarrier.try_wait.parity.acquire.cta.shared::cta.b64 p, [%1], %2;\n\t" \
        "selp.b32 %0, 1, 0, p;\n\t}" : "=r"(_d) : "r"(_m), "r"(_p) : "memory"); \
    if (!_d) {                                                                  \
        asm volatile("{\n\t.reg .pred P;\n\tWL%=:\n\t"                          \
            "mbarrier.try_wait.parity.acquire.cta.shared::cta.b64 P, [%0], %1, 0x989680;\n\t" \
            "@P bra.uni WD%=;\n\tbra.uni WL%=;\n\tWD%=:\n\t}"                   \
            :: "r"(_m), "r"(_p) : "memory");                                    \
    }                                                                           \
} while (0)
static __device__ __forceinline__ void bulk_g2s(uint32_t dst, const void* src,
                                                uint32_t bytes, uint32_t mbar) {
    asm volatile(
        "cp.async.bulk.shared::cluster.global.mbarrier::complete_tx::bytes [%0], [%1], %2, [%3];"
        :: "r"(dst), "l"(src), "r"(bytes), "r"(mbar) : "memory");
}
static __device__ __forceinline__ void ldsm_x4(uint32_t& r0, uint32_t& r1, uint32_t& r2,
                                               uint32_t& r3, uint32_t addr) {
    asm volatile("ldmatrix.sync.aligned.m8n8.x4.shared.b16 {%0,%1,%2,%3}, [%4];"
                 : "=r"(r0), "=r"(r1), "=r"(r2), "=r"(r3) : "r"(addr));
}
static __device__ __forceinline__ void mma16816(float* d, const uint32_t* a, const uint32_t* b) {
    asm volatile(
        "mma.sync.aligned.m16n8k16.row.col.f32.f16.f16.f32 "
        "{%0,%1,%2,%3}, {%4,%5,%6,%7}, {%8,%9}, {%0,%1,%2,%3};"
        : "+f"(d[0]), "+f"(d[1]), "+f"(d[2]), "+f"(d[3])
        : "r"(a[0]), "r"(a[1]), "r"(a[2]), "r"(a[3]), "r"(b[0]), "r"(b[1]));
}

// ============================================================================
// Kernel 1: prep = first linear (blocks 0..511) + W2 quant/swizzle (512..1023)
// (R15 version — measured 7.6us total overhead; R16's "faster" variant had
//  8-way bank-conflicted ws_t fills and regressed.)
// ============================================================================
__global__ void __launch_bounds__(256) k_prep(const float* __restrict__ x,
                                              const float* __restrict__ y,
                                              const float* __restrict__ W1,
                                              const float* __restrict__ b1,
                                              const float* __restrict__ W2) {
    int b = blockIdx.x;
    if (b >= 512) {
        // quant: 2 consecutive h per thread; layout = 16 slabs of 32KB
        int idx = ((b - 512) * 256 + threadIdx.x) * 2;
        int n = idx >> 9, h = idx & 511;
        int n_local = n & 127;
        int sid = (n >> 7) * 4 + (h >> 7);
        int k_local = h & 127;
        uint32_t c = (uint32_t)(k_local >> 3);
        uint32_t off = (uint32_t)n_local * 256 +
                       ((c ^ (uint32_t)(n_local & 7)) << 4) + (uint32_t)(k_local & 7) * 2;
        float2 v = *(const float2*)(W2 + (size_t)n * HH + h);
        __half2 hv;
        hv.x = __float2half_rn(v.x);
        hv.y = __float2half_rn(v.y);
        *(uint32_t*)(g_Wsw + (size_t)sid * 32768 + off) = *(uint32_t*)&hv;
        return;
    }
    __shared__ float xs_t[128][33];
    __shared__ float ws[32][128];
    int path = b >> 8;
    int rem = b & 255;
    int i0 = (rem & 15) * 32, h0 = (rem >> 4) * 32;
    const float* src = path ? y : x;
    int colOff = path ? 128 : 0;

    for (int v = threadIdx.x; v < 32 * 128; v += 256) {
        int i = v >> 7, d = v & 127;
        xs_t[d][i] = src[(i0 + i) * 128 + d];
    }
    for (int v = threadIdx.x; v < 32 * 32; v += 256) {
        int r = v >> 5, c4 = v & 31;
        ((float4*)&ws[r][0])[c4] = ((const float4*)&W1[(h0 + r) * 256 + colOff])[c4];
    }
    __syncthreads();

    int ti = threadIdx.x & 31, th = threadIdx.x >> 5;
    float acc0 = 0.f, acc1 = 0.f, acc2 = 0.f, acc3 = 0.f;
    #pragma unroll 4
    for (int d = 0; d < 128; d++) {
        float xv = xs_t[d][ti];
        acc0 = fmaf(xv, ws[th * 4 + 0][d], acc0);
        acc1 = fmaf(xv, ws[th * 4 + 1][d], acc1);
        acc2 = fmaf(xv, ws[th * 4 + 2][d], acc2);
        acc3 = fmaf(xv, ws[th * 4 + 3][d], acc3);
    }
    float* dst = path ? g_hy : g_hx;
    int i = i0 + ti;
    int hb = h0 + th * 4;
    float a0 = path ? 0.f : b1[hb + 0];
    float a1 = path ? 0.f : b1[hb + 1];
    float a2 = path ? 0.f : b1[hb + 2];
    float a3 = path ? 0.f : b1[hb + 3];
    dst[i * HH + hb + 0] = acc0 + a0;
    dst[i * HH + hb + 1] = acc1 + a1;
    dst[i * HH + hb + 2] = acc2 + a2;
    dst[i * HH + hb + 3] = acc3 + a3;
}

// ============================================================================
// Kernel 2: persistent main pair-GEMM + fused epilogue.
//   grid 148 (1 CTA/SM), block 256 (8 warps).  Tile: 128 pairs (8i x 16j),
//   16 steps of 32KB W (n128 x k128), pipeline continuous across tiles
//   (global step gst).  Warp grid 2m x 4n, warp tile m64 x n32.
//   A-build fully register-prefetched (hyv[16] + hxv[8]); early refetch bump.
// ============================================================================
__global__ void __launch_bounds__(256, 1) k_main(const float* __restrict__ b2g,
                                                 const float* __restrict__ w3g,
                                                 const float* __restrict__ b3g,
                                                 float* __restrict__ out) {
    extern __shared__ __align__(1024) unsigned char smem[];
    uint32_t sb = smem_u32(smem);
    int tid = threadIdx.x, wid = tid >> 5, lane = tid & 31;

    float* b2s = (float*)(smem + OFF_B2);
    float* w3s = (float*)(smem + OFF_W3);
    float* part = (float*)(smem + OFF_PART);

    // tiles handled by this CTA
    int ntiles = 0;
    for (int t = blockIdx.x; t < NTILE; t += NCTA) ntiles++;
    int total_gst = ntiles * 16;

    // ---- one-time init: mbarriers/counters + first two W slabs + b2/w3 ----
    if (tid == 0) {
        MBAR_INIT(sb + OFF_MB + 0, 1);
        MBAR_INIT(sb + OFF_MB + 8, 1);
        *(int*)(smem + OFF_MB + 16) = 0;
        *(int*)(smem + OFF_MB + 20) = 0;
        asm volatile("fence.proxy.async.shared::cta;" ::: "memory");
        MBAR_EXPECT_TX(sb + OFF_MB + 0, 32768u);
        bulk_g2s(sb + OFF_W(0), g_Wsw + 0 * 32768, 32768u, sb + OFF_MB + 0);
        MBAR_EXPECT_TX(sb + OFF_MB + 8, 32768u);
        bulk_g2s(sb + OFF_W(1), g_Wsw + 1 * 32768, 32768u, sb + OFF_MB + 8);
    }
    for (int v = tid; v < 512; v += 256) {
        b2s[v] = b2g[v];
        w3s[v] = w3g[v];
    }
    float b3v = b3g[0];

    // ---- lane geometry (tile-independent): warp grid 2m x 4n, m64 x n32 ----
    int wm = wid >> 2;          // 0..1 -> m0 = wm*64
    int wn = wid & 3;           // 0..3 -> n0 = wn*32 within n-chunk 128
    int m0 = wm * 64, n0 = wn * 32;

    uint32_t x7 = (uint32_t)(lane & 7);
    uint32_t aHi = (uint32_t)(lane >> 4);
    uint32_t aRow[4];
    #pragma unroll
    for (int mi = 0; mi < 4; mi++)
        aRow[mi] = sb + OFF_A + (uint32_t)(m0 + mi * 16 + (lane & 15)) * 1024;
    uint32_t bRowOff = (uint32_t)(n0 + (lane & 7) + ((lane >> 4) << 3)) * 256;
    uint32_t bHi = (uint32_t)((lane >> 3) & 1);

    int gst = 0;

    #pragma unroll 1
    for (int t = blockIdx.x; t < NTILE; t += NCTA) {
        int i0 = (t >> 5) * 8, j0 = (t & 31) * 16;

        // ---- tile boundary: all warps done with previous A / part ----
        __syncthreads();

        // ---- build A = relu(hx_i + hy_j) fp16; hx AND hy fully prefetched ----
        {
            int kk = tid;  // half2 column 0..255
            float2 hyv[16];
            #pragma unroll
            for (int j = 0; j < 16; j++)
                hyv[j] = ((const float2*)(g_hy + (j0 + j) * HH))[kk];
            float2 hxv[8];
            #pragma unroll
            for (int ig = 0; ig < 8; ig++)
                hxv[ig] = ((const float2*)(g_hx + (i0 + ig) * HH))[kk];
            uint32_t base = sb + OFF_A + (uint32_t)(kk & 3) * 4;
            uint32_t chunk = (uint32_t)(kk >> 2);
            #pragma unroll
            for (int ig = 0; ig < 8; ig++) {
                #pragma unroll
                for (int j = 0; j < 16; j++) {
                    float s0 = hxv[ig].x + hyv[j].x;
                    float s1 = hxv[ig].y + hyv[j].y;
                    uint32_t h2, r;
                    asm("cvt.rn.f16x2.f32 %0, %1, %2;" : "=r"(h2) : "f"(s1), "f"(s0));
                    asm("max.f16x2 %0, %1, %2;" : "=r"(r) : "r"(h2), "r"(0u));
                    uint32_t p = (uint32_t)(ig * 16 + j);
                    uint32_t addr = base + p * 1024 + ((chunk ^ (p & 7)) << 4);
                    asm volatile("st.shared.b32 [%0], %1;"
                                 :: "r"(addr), "r"(r) : "memory");
                }
            }
        }
        __syncthreads();   // A visible (covers one-time init on first tile)

        float d[4][4][4];                 // [mi][ni][q]
        float rowacc[4][2];               // [mi][row half]
        #pragma unroll
        for (int mi = 0; mi < 4; mi++) { rowacc[mi][0] = 0.f; rowacc[mi][1] = 0.f; }

        #pragma unroll 1
        for (int st = 0; st < 16; st++, gst++) {
            int s = gst & 1, kq = st & 3;
            MBAR_WAIT(sb + OFF_MB + s * 8, (gst >> 1) & 1);

            if (kq == 0) {
                #pragma unroll
                for (int mi = 0; mi < 4; mi++)
                    #pragma unroll
                    for (int ni = 0; ni < 4; ni++)
                        #pragma unroll
                        for (int q = 0; q < 4; q++) d[mi][ni][q] = 0.f;
            }

            uint32_t bBase = sb + OFF_W(s) + bRowOff;
            uint32_t aChunk0 = (uint32_t)(kq * 16);

            #pragma unroll
            for (int kk = 0; kk < 8; kk++) {
                uint32_t aswz = (((aChunk0 + (uint32_t)(kk << 1) + aHi) ^ x7) << 4);
                uint32_t bswz = ((((uint32_t)(kk << 1) + bHi) ^ x7) << 4);
                uint32_t a[4][4], b0[4], b1[4];
                #pragma unroll
                for (int mi = 0; mi < 4; mi++)
                    ldsm_x4(a[mi][0], a[mi][1], a[mi][2], a[mi][3], aRow[mi] + aswz);
                ldsm_x4(b0[0], b0[1], b0[2], b0[3], bBase + bswz);
                ldsm_x4(b1[0], b1[1], b1[2], b1[3], bBase + 16 * 256 + bswz);
                #pragma unroll
                for (int mi = 0; mi < 4; mi++) {
                    mma16816(d[mi][0], a[mi], b0 + 0);
                    mma16816(d[mi][1], a[mi], b0 + 2);
                    mma16816(d[mi][2], a[mi], b1 + 0);
                    mma16816(d[mi][3], a[mi], b1 + 2);
                }
            }

            // refetch bump EARLY (before fold): all W(s) reads by this warp done
            if (lane == 0) {
                int old;
                asm volatile("atom.shared.add.s32 %0, [%1], 1;"
                             : "=r"(old) : "r"(sb + OFF_MB + 16 + s * 4) : "memory");
                if ((old & 7) == 7 && gst + 2 < total_gst) {
                    MBAR_EXPECT_TX(sb + OFF_MB + s * 8, 32768u);
                    bulk_g2s(sb + OFF_W(s), g_Wsw + (size_t)((gst + 2) & 15) * 32768,
                             32768u, sb + OFF_MB + s * 8);
                }
            }

            if (kq == 3) {
                // fold: rowacc += sum_n relu(D + b2[n]) * w3[n]
                int ncol = (st >> 2) * 128 + n0 + (lane & 3) * 2;
                #pragma unroll
                for (int ni = 0; ni < 4; ni++) {
                    int c0 = ncol + ni * 8, c1 = c0 + 1;
                    float bb0 = b2s[c0], bb1 = b2s[c1];
                    float ww0 = w3s[c0], ww1 = w3s[c1];
                    #pragma unroll
                    for (int mi = 0; mi < 4; mi++) {
                        rowacc[mi][0] = fmaf(fmaxf(d[mi][ni][0] + bb0, 0.f), ww0, rowacc[mi][0]);
                        rowacc[mi][0] = fmaf(fmaxf(d[mi][ni][1] + bb1, 0.f), ww1, rowacc[mi][0]);
                        rowacc[mi][1] = fmaf(fmaxf(d[mi][ni][2] + bb0, 0.f), ww0, rowacc[mi][1]);
                        rowacc[mi][1] = fmaf(fmaxf(d[mi][ni][3] + bb1, 0.f), ww1, rowacc[mi][1]);
                    }
                }
            }
        }

        // ---- epilogue: reduce across 4 lanes/row, then across 4 n-warps ----
        #pragma unroll
        for (int mi = 0; mi < 4; mi++)
            #pragma unroll
            for (int rh = 0; rh < 2; rh++) {
                rowacc[mi][rh] += __shfl_xor_sync(0xFFFFFFFFu, rowacc[mi][rh], 1);
                rowacc[mi][rh] += __shfl_xor_sync(0xFFFFFFFFu, rowacc[mi][rh], 2);
            }

        if ((lane & 3) == 0) {
            int g = lane >> 2;
            #pragma unroll
            for (int mi = 0; mi < 4; mi++)
                #pragma unroll
                for (int rh = 0; rh < 2; rh++) {
                    int m = m0 + mi * 16 + rh * 8 + g;
                    part[m * 4 + wn] = rowacc[mi][rh];
                }
        }
        __syncthreads();

        if (tid < 128) {
            float res = part[tid * 4 + 0] + part[tid * 4 + 1] +
                        part[tid * 4 + 2] + part[tid * 4 + 3] + b3v;
            int i = i0 + (tid >> 4);
            int j = j0 + (tid & 15);
            out[i * BB + j] = res;
        }
    }
}

// ============================================================================
// Host launcher
// ============================================================================
extern "C" void kernel_launch(void* const* d_in, const int* in_sizes, int n_in,
                              void* d_out, int out_size) {
    const float* x  = (const float*)d_in[0];
    const float* y  = (const float*)d_in[1];
    const float* W1 = (const float*)d_in[2];
    const float* b1 = (const float*)d_in[3];
    const float* W2 = (const float*)d_in[4];
    const float* b2 = (const float*)d_in[5];
    const float* W3 = (const float*)d_in[6];
    const float* b3 = (const float*)d_in[7];
    float* out = (float*)d_out;

    cudaFuncSetAttribute(k_main, cudaFuncAttributeMaxDynamicSharedMemorySize, SMEM_BYTES);

    k_prep<<<1024, 256>>>(x, y, W1, b1, W2);
    k_main<<<NCTA, 256, SMEM_BYTES>>>(b2, W3, b3, out);
}